// round 4
// baseline (speedup 1.0000x reference)
#include <cuda_runtime.h>

#define MAXN 100000

// ---------------- scratch (static device globals; no allocations allowed) ----
__device__ float g_agg[MAXN * 128];
__device__ float g_h[MAXN * 128];
__device__ float g_xA[MAXN * 128];
__device__ float g_xB[MAXN * 128];
__device__ float g_deg[MAXN];
__device__ float g_invdeg[MAXN];
__device__ float g_stats[256];   // [0:128) colsum, [128:256) colsumsq
__device__ float g_scale[128];
__device__ float g_shift[128];

// ---------------- f32x2 packed-FMA helpers (Blackwell) ----------------------
__device__ __forceinline__ unsigned long long pack2(float lo, float hi) {
    unsigned long long r;
    asm("mov.b64 %0, {%1, %2};" : "=l"(r) : "f"(lo), "f"(hi));
    return r;
}
__device__ __forceinline__ float2 unpack2(unsigned long long v) {
    float2 r;
    asm("mov.b64 {%0, %1}, %2;" : "=f"(r.x), "=f"(r.y) : "l"(v));
    return r;
}
__device__ __forceinline__ void fma2(unsigned long long& d, unsigned long long a,
                                     unsigned long long b) {
    asm("fma.rn.f32x2 %0, %1, %2, %0;" : "+l"(d) : "l"(a), "l"(b));
}

// ---------------- utility kernels -------------------------------------------
__global__ void zero_kernel(float4* p, int n4) {
    int i = blockIdx.x * blockDim.x + threadIdx.x;
    if (i < n4) p[i] = make_float4(0.f, 0.f, 0.f, 0.f);
}

__global__ void deg_kernel(const int* __restrict__ dst, float* __restrict__ deg, int E) {
    int e = blockIdx.x * blockDim.x + threadIdx.x;
    if (e < E) atomicAdd(&deg[dst[e]], 1.0f);
}

__global__ void invdeg_kernel(const float* __restrict__ deg, float* __restrict__ invdeg, int n) {
    int i = blockIdx.x * blockDim.x + threadIdx.x;
    if (i < n) invdeg[i] = 1.0f / fmaxf(deg[i], 1.0f);
}

// ---------------- edge aggregation: agg[dst] += x[src] ----------------------
// One thread per (edge, 4-float chunk). Gather is row-contiguous (coalesced),
// scatter uses float4 vector reduction (RED.128) on sm_90+.
template <int DIM>
__global__ void agg_kernel(const float* __restrict__ x, const int* __restrict__ src,
                           const int* __restrict__ dst, float* __restrict__ agg, int E) {
    constexpr int P = DIM / 4;
    int idx = blockIdx.x * blockDim.x + threadIdx.x;
    if (idx >= E * P) return;
    int e = idx / P;
    int part = idx - e * P;
    int s = src[e];
    int d = dst[e];
    float4 v = *reinterpret_cast<const float4*>(x + (size_t)s * DIM + part * 4);
    atomicAdd(reinterpret_cast<float4*>(agg + (size_t)d * DIM + part * 4), v);
}

// ---------------- fused GEMM + BN-stats -------------------------------------
// h[m][j] = sum_k x[m][k]*Ws[k][j] + (agg[m][k]*invdeg[m])*Wn[k][j] + bias[j]
// Treated as one GEMM with K = 2*DIN (A = [x | agg*invdeg], B = [Ws ; Wn]).
// BM=128, BN=128, BK=16, 256 threads; each thread: 8 rows (4 f32x2 row-pairs)
// x 8 cols (interleaved stride 16 -> conflict-free smem reads).
// Epilogue also reduces per-column sum / sumsq into g_stats via one atomic
// per column per block.
template <int DIN>
__global__ __launch_bounds__(256, 2) void gemm_stats_kernel(
    const float* __restrict__ x, const float* __restrict__ agg,
    const float* __restrict__ invdeg, const float* __restrict__ Ws,
    const float* __restrict__ Wn, const float* __restrict__ bias,
    float* __restrict__ h, float* __restrict__ stats, int n) {
    constexpr int K = 2 * DIN;
    constexpr int BM = 128, BK = 16;

    __shared__ float As[BK][BM + 2];                 // +2 keeps rows 8B-aligned
    __shared__ unsigned long long Bs[BK][128];       // W value duplicated in both halves

    int tid = threadIdx.x;
    int tx = tid & 15;    // column group: cols tx + 16*i
    int ty = tid >> 4;    // row group: rows ty*8 .. ty*8+7
    int row0 = blockIdx.x * BM;

    unsigned long long acc[4][8];
#pragma unroll
    for (int r = 0; r < 4; r++)
#pragma unroll
        for (int i = 0; i < 8; i++) acc[r][i] = 0ULL;

    int a_kq = tid & 3;   // which float4 along k
    int a_m = tid >> 2;   // row within tile (0..63, +64 on 2nd pass)
    int b_j4 = tid & 31;  // which float4 along j
    int b_k = tid >> 5;   // k row (0..7, +8 on 2nd pass)

    for (int k0 = 0; k0 < K; k0 += BK) {
        bool isAgg = (k0 >= DIN);
        const float* Asrc = isAgg ? agg : x;
        const float* Wsrc = isAgg ? Wn : Ws;
        int koff = isAgg ? (k0 - DIN) : k0;

        // ---- load A tile (transposed into As[k][m]) ----
#pragma unroll
        for (int pass = 0; pass < 2; pass++) {
            int m = a_m + pass * 64;
            int grow = row0 + m;
            float4 v = make_float4(0.f, 0.f, 0.f, 0.f);
            float idg = 1.0f;
            if (grow < n) {
                v = *reinterpret_cast<const float4*>(Asrc + (size_t)grow * DIN + koff + a_kq * 4);
                if (isAgg) idg = invdeg[grow];
            }
            As[a_kq * 4 + 0][m] = v.x * idg;
            As[a_kq * 4 + 1][m] = v.y * idg;
            As[a_kq * 4 + 2][m] = v.z * idg;
            As[a_kq * 4 + 3][m] = v.w * idg;
        }

        // ---- load B tile, pre-splat each weight into both f32x2 lanes ----
#pragma unroll
        for (int pass = 0; pass < 2; pass++) {
            int k = b_k + pass * 8;
            float4 v = *reinterpret_cast<const float4*>(Wsrc + (size_t)(koff + k) * 128 + b_j4 * 4);
            Bs[k][b_j4 * 4 + 0] = pack2(v.x, v.x);
            Bs[k][b_j4 * 4 + 1] = pack2(v.y, v.y);
            Bs[k][b_j4 * 4 + 2] = pack2(v.z, v.z);
            Bs[k][b_j4 * 4 + 3] = pack2(v.w, v.w);
        }
        __syncthreads();

#pragma unroll
        for (int k = 0; k < BK; k++) {
            unsigned long long a2[4];
#pragma unroll
            for (int r = 0; r < 4; r++)
                a2[r] = *reinterpret_cast<const unsigned long long*>(&As[k][ty * 8 + 2 * r]);
#pragma unroll
            for (int i = 0; i < 8; i++) {
                unsigned long long b = Bs[k][tx + 16 * i];
#pragma unroll
                for (int r = 0; r < 4; r++) fma2(acc[r][i], a2[r], b);
            }
        }
        __syncthreads();
    }

    // ---- epilogue: bias, store, per-column partial stats ----
    float bfrag[8];
#pragma unroll
    for (int i = 0; i < 8; i++) bfrag[i] = bias[tx + 16 * i];

    float psum[8], psumsq[8];
#pragma unroll
    for (int i = 0; i < 8; i++) { psum[i] = 0.f; psumsq[i] = 0.f; }

#pragma unroll
    for (int r = 0; r < 4; r++) {
        int m0 = row0 + ty * 8 + 2 * r;
#pragma unroll
        for (int half = 0; half < 2; half++) {
            int m = m0 + half;
            if (m < n) {
#pragma unroll
                for (int i = 0; i < 8; i++) {
                    float2 v2 = unpack2(acc[r][i]);
                    float v = (half == 0 ? v2.x : v2.y) + bfrag[i];
                    h[(size_t)m * 128 + tx + 16 * i] = v;
                    psum[i] += v;
                    psumsq[i] += v * v;
                }
            }
        }
    }

    __syncthreads();
    float* red1 = &As[0][0];                                  // 2080 floats >= 2048
    float* red2 = reinterpret_cast<float*>(&Bs[0][0]);        // 4096 floats
#pragma unroll
    for (int i = 0; i < 8; i++) {
        red1[ty * 128 + tx + 16 * i] = psum[i];
        red2[ty * 128 + tx + 16 * i] = psumsq[i];
    }
    __syncthreads();
    if (tid < 128) {
        float s = 0.f, q = 0.f;
#pragma unroll
        for (int t = 0; t < 16; t++) {
            s += red1[t * 128 + tid];
            q += red2[t * 128 + tid];
        }
        atomicAdd(&stats[tid], s);
        atomicAdd(&stats[128 + tid], q);
    }
}

// ---------------- BN parameter folding: scale/shift per column --------------
__global__ void bnparam_kernel(const float* __restrict__ stats, const float* __restrict__ gamma,
                               const float* __restrict__ beta, float* __restrict__ scale,
                               float* __restrict__ shift, float invN) {
    int j = threadIdx.x;
    float mu = stats[j] * invN;
    float var = stats[128 + j] * invN - mu * mu;
    float sc = gamma[j] * rsqrtf(var + 1e-5f);
    scale[j] = sc;
    shift[j] = fmaf(-mu, sc, beta[j]);
}

// ---------------- BN apply + ReLU (elementwise, float4) ---------------------
__global__ void bn_relu_kernel(const float* __restrict__ h, const float* __restrict__ scale,
                               const float* __restrict__ shift, float* __restrict__ out, int n) {
    int idx = blockIdx.x * blockDim.x + threadIdx.x;
    if (idx >= n * 32) return;
    int j4 = idx & 31;
    float4 v = reinterpret_cast<const float4*>(h)[idx];
    float4 sc = reinterpret_cast<const float4*>(scale)[j4];
    float4 sh = reinterpret_cast<const float4*>(shift)[j4];
    float4 o;
    o.x = fmaxf(fmaf(v.x, sc.x, sh.x), 0.f);
    o.y = fmaxf(fmaf(v.y, sc.y, sh.y), 0.f);
    o.z = fmaxf(fmaf(v.z, sc.z, sh.z), 0.f);
    o.w = fmaxf(fmaf(v.w, sc.w, sh.w), 0.f);
    reinterpret_cast<float4*>(out)[idx] = o;
}

// ---------------- fused BN + ReLU + classifier (final layer) ----------------
// One warp per node row: normalize 128 values, dot with Wc[128,2], warp-reduce.
__global__ void bn_cls_kernel(const float* __restrict__ h, const float* __restrict__ scale,
                              const float* __restrict__ shift, const float* __restrict__ Wc,
                              const float* __restrict__ bc, float* __restrict__ out, int n) {
    int warp = (blockIdx.x * blockDim.x + threadIdx.x) >> 5;
    int lane = threadIdx.x & 31;
    if (warp >= n) return;
    float4 v = reinterpret_cast<const float4*>(h + (size_t)warp * 128)[lane];
    float4 sc = reinterpret_cast<const float4*>(scale)[lane];
    float4 sh = reinterpret_cast<const float4*>(shift)[lane];
    int c = lane * 4;
    float w0 = fmaxf(fmaf(v.x, sc.x, sh.x), 0.f);
    float w1 = fmaxf(fmaf(v.y, sc.y, sh.y), 0.f);
    float w2 = fmaxf(fmaf(v.z, sc.z, sh.z), 0.f);
    float w3 = fmaxf(fmaf(v.w, sc.w, sh.w), 0.f);
    float a0 = w0 * Wc[(c + 0) * 2 + 0] + w1 * Wc[(c + 1) * 2 + 0] +
               w2 * Wc[(c + 2) * 2 + 0] + w3 * Wc[(c + 3) * 2 + 0];
    float a1 = w0 * Wc[(c + 0) * 2 + 1] + w1 * Wc[(c + 1) * 2 + 1] +
               w2 * Wc[(c + 2) * 2 + 1] + w3 * Wc[(c + 3) * 2 + 1];
#pragma unroll
    for (int off = 16; off; off >>= 1) {
        a0 += __shfl_xor_sync(0xffffffffu, a0, off);
        a1 += __shfl_xor_sync(0xffffffffu, a1, off);
    }
    if (lane == 0) {
        out[(size_t)warp * 2 + 0] = a0 + bc[0];
        out[(size_t)warp * 2 + 1] = a1 + bc[1];
    }
}

// ---------------- host entry -------------------------------------------------
extern "C" void kernel_launch(void* const* d_in, const int* in_sizes, int n_in,
                              void* d_out, int out_size) {
    const float* x = (const float*)d_in[0];
    const int* src = (const int*)d_in[1];
    const int* dst = (const int*)d_in[2];
    const float* Ws0 = (const float*)d_in[3];
    const float* b0 = (const float*)d_in[4];
    const float* Wn0 = (const float*)d_in[5];
    const float* g0 = (const float*)d_in[6];
    const float* be0 = (const float*)d_in[7];
    const float* Ws1 = (const float*)d_in[8];
    const float* b1 = (const float*)d_in[9];
    const float* Wn1 = (const float*)d_in[10];
    const float* g1 = (const float*)d_in[11];
    const float* be1 = (const float*)d_in[12];
    const float* Ws2 = (const float*)d_in[13];
    const float* b2 = (const float*)d_in[14];
    const float* Wn2 = (const float*)d_in[15];
    const float* g2 = (const float*)d_in[16];
    const float* be2 = (const float*)d_in[17];
    const float* Wc = (const float*)d_in[18];
    const float* bc = (const float*)d_in[19];
    float* out = (float*)d_out;

    int n = in_sizes[0] / 64;
    int E = in_sizes[1];
    float invN = 1.0f / (float)n;

    float *agg, *h, *xA, *xB, *deg, *invdeg, *stats, *scale, *shift;
    cudaGetSymbolAddress((void**)&agg, g_agg);
    cudaGetSymbolAddress((void**)&h, g_h);
    cudaGetSymbolAddress((void**)&xA, g_xA);
    cudaGetSymbolAddress((void**)&xB, g_xB);
    cudaGetSymbolAddress((void**)&deg, g_deg);
    cudaGetSymbolAddress((void**)&invdeg, g_invdeg);
    cudaGetSymbolAddress((void**)&stats, g_stats);
    cudaGetSymbolAddress((void**)&scale, g_scale);
    cudaGetSymbolAddress((void**)&shift, g_shift);

    const int T = 256;
    int gb = (n + 127) / 128;

    // degrees (shared by all layers)
    zero_kernel<<<(n / 4 + T - 1) / T, T>>>((float4*)deg, n / 4);
    deg_kernel<<<(E + T - 1) / T, T>>>(dst, deg, E);
    invdeg_kernel<<<(n + T - 1) / T, T>>>(deg, invdeg, n);

    // ---- layer 0 (DIN = 64) ----
    zero_kernel<<<(n * 16 + T - 1) / T, T>>>((float4*)agg, n * 16);
    zero_kernel<<<1, 64>>>((float4*)stats, 64);
    agg_kernel<64><<<(E * 16 + T - 1) / T, T>>>(x, src, dst, agg, E);
    gemm_stats_kernel<64><<<gb, T>>>(x, agg, invdeg, Ws0, Wn0, b0, h, stats, n);
    bnparam_kernel<<<1, 128>>>(stats, g0, be0, scale, shift, invN);
    bn_relu_kernel<<<(n * 32 + T - 1) / T, T>>>(h, scale, shift, xA, n);

    // ---- layer 1 (DIN = 128) ----
    zero_kernel<<<(n * 32 + T - 1) / T, T>>>((float4*)agg, n * 32);
    zero_kernel<<<1, 64>>>((float4*)stats, 64);
    agg_kernel<128><<<(E * 32 + T - 1) / T, T>>>(xA, src, dst, agg, E);
    gemm_stats_kernel<128><<<gb, T>>>(xA, agg, invdeg, Ws1, Wn1, b1, h, stats, n);
    bnparam_kernel<<<1, 128>>>(stats, g1, be1, scale, shift, invN);
    bn_relu_kernel<<<(n * 32 + T - 1) / T, T>>>(h, scale, shift, xB, n);

    // ---- layer 2 (DIN = 128) + fused BN/ReLU/classifier ----
    zero_kernel<<<(n * 32 + T - 1) / T, T>>>((float4*)agg, n * 32);
    zero_kernel<<<1, 64>>>((float4*)stats, 64);
    agg_kernel<128><<<(E * 32 + T - 1) / T, T>>>(xB, src, dst, agg, E);
    gemm_stats_kernel<128><<<gb, T>>>(xB, agg, invdeg, Ws2, Wn2, b2, h, stats, n);
    bnparam_kernel<<<1, 128>>>(stats, g2, be2, scale, shift, invN);
    // FIX (R3): one warp per node -> need n*32 threads (was n*8: only 1/4 of
    // nodes written, rest stayed 0xAA-poisoned -> rel_err = sqrt(3)/2 = 0.866).
    bn_cls_kernel<<<(n * 32 + T - 1) / T, T>>>(h, scale, shift, Wc, bc, out, n);
}

// round 5
// speedup vs baseline: 2.0177x; 2.0177x over previous
#include <cuda_runtime.h>

#define MAXN 100000
#define MAXE 1300000

// ---------------- scratch (static device globals; no allocations allowed) ----
__device__ float g_neigh[MAXN * 128];
__device__ float g_h[MAXN * 128];
__device__ float g_xA[MAXN * 128];
__device__ float g_xB[MAXN * 128];
__device__ int   g_cnt[MAXN];
__device__ int   g_rowptr[MAXN];
__device__ int   g_cursor[MAXN];
__device__ int   g_bsum[128];
__device__ int   g_eidx[MAXE];
__device__ float g_stats[256];   // [0:128) colsum, [128:256) colsumsq
__device__ float g_scale[128];
__device__ float g_shift[128];

// ---------------- f32x2 packed-FMA helpers (Blackwell) ----------------------
__device__ __forceinline__ unsigned long long pack2(float lo, float hi) {
    unsigned long long r;
    asm("mov.b64 %0, {%1, %2};" : "=l"(r) : "f"(lo), "f"(hi));
    return r;
}
__device__ __forceinline__ float2 unpack2(unsigned long long v) {
    float2 r;
    asm("mov.b64 {%0, %1}, %2;" : "=f"(r.x), "=f"(r.y) : "l"(v));
    return r;
}
__device__ __forceinline__ void fma2(unsigned long long& d, unsigned long long a,
                                     unsigned long long b) {
    asm("fma.rn.f32x2 %0, %1, %2, %0;" : "+l"(d) : "l"(a), "l"(b));
}

// ---------------- utility kernels -------------------------------------------
__global__ void zero_kernel(float4* p, int n4) {
    int i = blockIdx.x * blockDim.x + threadIdx.x;
    if (i < n4) p[i] = make_float4(0.f, 0.f, 0.f, 0.f);
}

// ---------------- CSR build --------------------------------------------------
__global__ void count_kernel(const int* __restrict__ dst, int* __restrict__ cnt, int E) {
    int e = blockIdx.x * blockDim.x + threadIdx.x;
    if (e < E) atomicAdd(&cnt[dst[e]], 1);
}

// scan1: per-block (2048 elems) exclusive scan of cnt -> rowptr, block sums -> bsum
__global__ void scan1_kernel(const int* __restrict__ cnt, int* __restrict__ rowptr,
                             int* __restrict__ bsum, int n) {
    __shared__ int sdata[256];
    int b = blockIdx.x, t = threadIdx.x;
    int base = b * 2048 + t * 8;
    int v[8], s = 0;
#pragma unroll
    for (int i = 0; i < 8; i++) {
        int idx = base + i;
        v[i] = (idx < n) ? cnt[idx] : 0;
        s += v[i];
    }
    sdata[t] = s;
    __syncthreads();
    // Kogge-Stone inclusive scan over 256 thread sums
    for (int off = 1; off < 256; off <<= 1) {
        int xv = (t >= off) ? sdata[t - off] : 0;
        __syncthreads();
        sdata[t] += xv;
        __syncthreads();
    }
    int run = sdata[t] - s;  // exclusive prefix for this thread
    if (t == 255) bsum[b] = sdata[255];
#pragma unroll
    for (int i = 0; i < 8; i++) {
        int idx = base + i;
        if (idx < n) rowptr[idx] = run;
        run += v[i];
    }
}

__global__ void scan2_kernel(int* __restrict__ bsum, int nb) {
    if (threadIdx.x == 0) {
        int s = 0;
        for (int i = 0; i < nb; i++) { int t = bsum[i]; bsum[i] = s; s += t; }
    }
}

__global__ void scan3_kernel(int* __restrict__ rowptr, const int* __restrict__ bsum, int n) {
    int i = blockIdx.x * blockDim.x + threadIdx.x;
    if (i < n) rowptr[i] += bsum[i >> 11];
}

__global__ void fill_kernel(const int* __restrict__ src, const int* __restrict__ dst,
                            const int* __restrict__ rowptr, int* __restrict__ cursor,
                            int* __restrict__ eidx, int E) {
    int e = blockIdx.x * blockDim.x + threadIdx.x;
    if (e < E) {
        int d = dst[e];
        int p = atomicAdd(&cursor[d], 1);
        eidx[rowptr[d] + p] = src[e];
    }
}

// ---------------- mean aggregation via CSR gather ----------------------------
// One warp per node. Lane owns DIM/32 contiguous floats of the row. Neighbor
// indices are uniform broadcast loads; row reads are fully coalesced (256/512B).
// Unroll-4 gives MLP>=4 independent L2 loads. Writes normalized mean once.
template <int DIM>
__global__ void gather_kernel(const float* __restrict__ x, const int* __restrict__ eidx,
                              const int* __restrict__ rowptr, const int* __restrict__ cnt,
                              float* __restrict__ neigh, int n) {
    int node = blockIdx.x * (blockDim.x >> 5) + (threadIdx.x >> 5);
    int lane = threadIdx.x & 31;
    if (node >= n) return;
    int start = rowptr[node];
    int d = cnt[node];

    if (DIM == 128) {
        float4 a0 = make_float4(0.f, 0.f, 0.f, 0.f);
        float4 a1 = make_float4(0.f, 0.f, 0.f, 0.f);
        int j = 0;
        for (; j + 4 <= d; j += 4) {
            int s0 = eidx[start + j + 0];
            int s1 = eidx[start + j + 1];
            int s2 = eidx[start + j + 2];
            int s3 = eidx[start + j + 3];
            float4 v0 = *reinterpret_cast<const float4*>(x + (size_t)s0 * 128 + lane * 4);
            float4 v1 = *reinterpret_cast<const float4*>(x + (size_t)s1 * 128 + lane * 4);
            float4 v2 = *reinterpret_cast<const float4*>(x + (size_t)s2 * 128 + lane * 4);
            float4 v3 = *reinterpret_cast<const float4*>(x + (size_t)s3 * 128 + lane * 4);
            a0.x += v0.x + v1.x; a0.y += v0.y + v1.y; a0.z += v0.z + v1.z; a0.w += v0.w + v1.w;
            a1.x += v2.x + v3.x; a1.y += v2.y + v3.y; a1.z += v2.z + v3.z; a1.w += v2.w + v3.w;
        }
        for (; j < d; j++) {
            int s = eidx[start + j];
            float4 v = *reinterpret_cast<const float4*>(x + (size_t)s * 128 + lane * 4);
            a0.x += v.x; a0.y += v.y; a0.z += v.z; a0.w += v.w;
        }
        float inv = 1.0f / (float)max(d, 1);
        float4 o;
        o.x = (a0.x + a1.x) * inv; o.y = (a0.y + a1.y) * inv;
        o.z = (a0.z + a1.z) * inv; o.w = (a0.w + a1.w) * inv;
        *reinterpret_cast<float4*>(neigh + (size_t)node * 128 + lane * 4) = o;
    } else {  // DIM == 64
        float2 a0 = make_float2(0.f, 0.f);
        float2 a1 = make_float2(0.f, 0.f);
        int j = 0;
        for (; j + 4 <= d; j += 4) {
            int s0 = eidx[start + j + 0];
            int s1 = eidx[start + j + 1];
            int s2 = eidx[start + j + 2];
            int s3 = eidx[start + j + 3];
            float2 v0 = *reinterpret_cast<const float2*>(x + (size_t)s0 * 64 + lane * 2);
            float2 v1 = *reinterpret_cast<const float2*>(x + (size_t)s1 * 64 + lane * 2);
            float2 v2 = *reinterpret_cast<const float2*>(x + (size_t)s2 * 64 + lane * 2);
            float2 v3 = *reinterpret_cast<const float2*>(x + (size_t)s3 * 64 + lane * 2);
            a0.x += v0.x + v1.x; a0.y += v0.y + v1.y;
            a1.x += v2.x + v3.x; a1.y += v2.y + v3.y;
        }
        for (; j < d; j++) {
            int s = eidx[start + j];
            float2 v = *reinterpret_cast<const float2*>(x + (size_t)s * 64 + lane * 2);
            a0.x += v.x; a0.y += v.y;
        }
        float inv = 1.0f / (float)max(d, 1);
        float2 o;
        o.x = (a0.x + a1.x) * inv; o.y = (a0.y + a1.y) * inv;
        *reinterpret_cast<float2*>(neigh + (size_t)node * 64 + lane * 2) = o;
    }
}

// ---------------- fused GEMM + BN-stats -------------------------------------
// h[m][j] = sum_k x[m][k]*Ws[k][j] + neigh[m][k]*Wn[k][j] + bias[j]
// One GEMM with K = 2*DIN (A = [x | neigh], B = [Ws ; Wn]). BM=128, BK=16,
// 256 threads; thread tile 8 rows (4 f32x2 pairs) x 8 cols (stride-16).
// Epilogue reduces per-column sum/sumsq into g_stats (1 atomic/col/block).
template <int DIN>
__global__ __launch_bounds__(256, 2) void gemm_stats_kernel(
    const float* __restrict__ x, const float* __restrict__ neigh,
    const float* __restrict__ Ws, const float* __restrict__ Wn,
    const float* __restrict__ bias, float* __restrict__ h,
    float* __restrict__ stats, int n) {
    constexpr int K = 2 * DIN;
    constexpr int BM = 128, BK = 16;

    __shared__ float As[BK][BM + 4];                 // +4: rows 16B-aligned
    __shared__ unsigned long long Bs[BK][128];       // weight splatted to both lanes

    int tid = threadIdx.x;
    int tx = tid & 15;    // column group: cols tx + 16*i
    int ty = tid >> 4;    // row group: rows ty*8 .. ty*8+7
    int row0 = blockIdx.x * BM;

    unsigned long long acc[4][8];
#pragma unroll
    for (int r = 0; r < 4; r++)
#pragma unroll
        for (int i = 0; i < 8; i++) acc[r][i] = 0ULL;

    int a_kq = tid & 3;   // which float4 along k
    int a_m = tid >> 2;   // row within tile (0..63, +64 on 2nd pass)
    int b_j4 = tid & 31;  // which float4 along j
    int b_k = tid >> 5;   // k row (0..7, +8 on 2nd pass)

    for (int k0 = 0; k0 < K; k0 += BK) {
        bool isAgg = (k0 >= DIN);
        const float* Asrc = isAgg ? neigh : x;
        const float* Wsrc = isAgg ? Wn : Ws;
        int koff = isAgg ? (k0 - DIN) : k0;

        // ---- load A tile (transposed into As[k][m]) ----
#pragma unroll
        for (int pass = 0; pass < 2; pass++) {
            int m = a_m + pass * 64;
            int grow = row0 + m;
            float4 v = make_float4(0.f, 0.f, 0.f, 0.f);
            if (grow < n)
                v = *reinterpret_cast<const float4*>(Asrc + (size_t)grow * DIN + koff + a_kq * 4);
            As[a_kq * 4 + 0][m] = v.x;
            As[a_kq * 4 + 1][m] = v.y;
            As[a_kq * 4 + 2][m] = v.z;
            As[a_kq * 4 + 3][m] = v.w;
        }

        // ---- load B tile, pre-splat each weight into both f32x2 lanes ----
#pragma unroll
        for (int pass = 0; pass < 2; pass++) {
            int k = b_k + pass * 8;
            float4 v = *reinterpret_cast<const float4*>(Wsrc + (size_t)(koff + k) * 128 + b_j4 * 4);
            Bs[k][b_j4 * 4 + 0] = pack2(v.x, v.x);
            Bs[k][b_j4 * 4 + 1] = pack2(v.y, v.y);
            Bs[k][b_j4 * 4 + 2] = pack2(v.z, v.z);
            Bs[k][b_j4 * 4 + 3] = pack2(v.w, v.w);
        }
        __syncthreads();

#pragma unroll
        for (int k = 0; k < BK; k++) {
            unsigned long long a2[4];
            // 8 consecutive floats, 16B-aligned -> 2x LDS.128
            ulonglong2 p0 = *reinterpret_cast<const ulonglong2*>(&As[k][ty * 8 + 0]);
            ulonglong2 p1 = *reinterpret_cast<const ulonglong2*>(&As[k][ty * 8 + 4]);
            a2[0] = p0.x; a2[1] = p0.y; a2[2] = p1.x; a2[3] = p1.y;
#pragma unroll
            for (int i = 0; i < 8; i++) {
                unsigned long long b = Bs[k][tx + 16 * i];
#pragma unroll
                for (int r = 0; r < 4; r++) fma2(acc[r][i], a2[r], b);
            }
        }
        __syncthreads();
    }

    // ---- epilogue: bias, store, per-column partial stats ----
    float bfrag[8];
#pragma unroll
    for (int i = 0; i < 8; i++) bfrag[i] = bias[tx + 16 * i];

    float psum[8], psumsq[8];
#pragma unroll
    for (int i = 0; i < 8; i++) { psum[i] = 0.f; psumsq[i] = 0.f; }

#pragma unroll
    for (int r = 0; r < 4; r++) {
        int m0 = row0 + ty * 8 + 2 * r;
#pragma unroll
        for (int half = 0; half < 2; half++) {
            int m = m0 + half;
            if (m < n) {
#pragma unroll
                for (int i = 0; i < 8; i++) {
                    float2 v2 = unpack2(acc[r][i]);
                    float v = (half == 0 ? v2.x : v2.y) + bfrag[i];
                    h[(size_t)m * 128 + tx + 16 * i] = v;
                    psum[i] += v;
                    psumsq[i] += v * v;
                }
            }
        }
    }

    __syncthreads();
    float* red1 = &As[0][0];                                  // >= 2048 floats
    float* red2 = reinterpret_cast<float*>(&Bs[0][0]);        // 4096 floats
#pragma unroll
    for (int i = 0; i < 8; i++) {
        red1[ty * 128 + tx + 16 * i] = psum[i];
        red2[ty * 128 + tx + 16 * i] = psumsq[i];
    }
    __syncthreads();
    if (tid < 128) {
        float s = 0.f, q = 0.f;
#pragma unroll
        for (int t = 0; t < 16; t++) {
            s += red1[t * 128 + tid];
            q += red2[t * 128 + tid];
        }
        atomicAdd(&stats[tid], s);
        atomicAdd(&stats[128 + tid], q);
    }
}

// ---------------- BN parameter folding: scale/shift per column --------------
__global__ void bnparam_kernel(const float* __restrict__ stats, const float* __restrict__ gamma,
                               const float* __restrict__ beta, float* __restrict__ scale,
                               float* __restrict__ shift, float invN) {
    int j = threadIdx.x;
    float mu = stats[j] * invN;
    float var = stats[128 + j] * invN - mu * mu;
    float sc = gamma[j] * rsqrtf(var + 1e-5f);
    scale[j] = sc;
    shift[j] = fmaf(-mu, sc, beta[j]);
}

// ---------------- BN apply + ReLU (elementwise, float4) ---------------------
__global__ void bn_relu_kernel(const float* __restrict__ h, const float* __restrict__ scale,
                               const float* __restrict__ shift, float* __restrict__ out, int n) {
    int idx = blockIdx.x * blockDim.x + threadIdx.x;
    if (idx >= n * 32) return;
    int j4 = idx & 31;
    float4 v = reinterpret_cast<const float4*>(h)[idx];
    float4 sc = reinterpret_cast<const float4*>(scale)[j4];
    float4 sh = reinterpret_cast<const float4*>(shift)[j4];
    float4 o;
    o.x = fmaxf(fmaf(v.x, sc.x, sh.x), 0.f);
    o.y = fmaxf(fmaf(v.y, sc.y, sh.y), 0.f);
    o.z = fmaxf(fmaf(v.z, sc.z, sh.z), 0.f);
    o.w = fmaxf(fmaf(v.w, sc.w, sh.w), 0.f);
    reinterpret_cast<float4*>(out)[idx] = o;
}

// ---------------- fused BN + ReLU + classifier (final layer) ----------------
// One warp per node row: normalize 128 values, dot with Wc[128,2], warp-reduce.
__global__ void bn_cls_kernel(const float* __restrict__ h, const float* __restrict__ scale,
                              const float* __restrict__ shift, const float* __restrict__ Wc,
                              const float* __restrict__ bc, float* __restrict__ out, int n) {
    int warp = (blockIdx.x * blockDim.x + threadIdx.x) >> 5;
    int lane = threadIdx.x & 31;
    if (warp >= n) return;
    float4 v = reinterpret_cast<const float4*>(h + (size_t)warp * 128)[lane];
    float4 sc = reinterpret_cast<const float4*>(scale)[lane];
    float4 sh = reinterpret_cast<const float4*>(shift)[lane];
    int c = lane * 4;
    float w0 = fmaxf(fmaf(v.x, sc.x, sh.x), 0.f);
    float w1 = fmaxf(fmaf(v.y, sc.y, sh.y), 0.f);
    float w2 = fmaxf(fmaf(v.z, sc.z, sh.z), 0.f);
    float w3 = fmaxf(fmaf(v.w, sc.w, sh.w), 0.f);
    float a0 = w0 * Wc[(c + 0) * 2 + 0] + w1 * Wc[(c + 1) * 2 + 0] +
               w2 * Wc[(c + 2) * 2 + 0] + w3 * Wc[(c + 3) * 2 + 0];
    float a1 = w0 * Wc[(c + 0) * 2 + 1] + w1 * Wc[(c + 1) * 2 + 1] +
               w2 * Wc[(c + 2) * 2 + 1] + w3 * Wc[(c + 3) * 2 + 1];
#pragma unroll
    for (int off = 16; off; off >>= 1) {
        a0 += __shfl_xor_sync(0xffffffffu, a0, off);
        a1 += __shfl_xor_sync(0xffffffffu, a1, off);
    }
    if (lane == 0) {
        out[(size_t)warp * 2 + 0] = a0 + bc[0];
        out[(size_t)warp * 2 + 1] = a1 + bc[1];
    }
}

// ---------------- host entry -------------------------------------------------
extern "C" void kernel_launch(void* const* d_in, const int* in_sizes, int n_in,
                              void* d_out, int out_size) {
    const float* x = (const float*)d_in[0];
    const int* src = (const int*)d_in[1];
    const int* dst = (const int*)d_in[2];
    const float* Ws0 = (const float*)d_in[3];
    const float* b0 = (const float*)d_in[4];
    const float* Wn0 = (const float*)d_in[5];
    const float* g0 = (const float*)d_in[6];
    const float* be0 = (const float*)d_in[7];
    const float* Ws1 = (const float*)d_in[8];
    const float* b1 = (const float*)d_in[9];
    const float* Wn1 = (const float*)d_in[10];
    const float* g1 = (const float*)d_in[11];
    const float* be1 = (const float*)d_in[12];
    const float* Ws2 = (const float*)d_in[13];
    const float* b2 = (const float*)d_in[14];
    const float* Wn2 = (const float*)d_in[15];
    const float* g2 = (const float*)d_in[16];
    const float* be2 = (const float*)d_in[17];
    const float* Wc = (const float*)d_in[18];
    const float* bc = (const float*)d_in[19];
    float* out = (float*)d_out;

    int n = in_sizes[0] / 64;
    int E = in_sizes[1];
    float invN = 1.0f / (float)n;

    float *neigh, *h, *xA, *xB, *stats, *scale, *shift;
    int *cnt, *rowptr, *cursor, *bsum, *eidx;
    cudaGetSymbolAddress((void**)&neigh, g_neigh);
    cudaGetSymbolAddress((void**)&h, g_h);
    cudaGetSymbolAddress((void**)&xA, g_xA);
    cudaGetSymbolAddress((void**)&xB, g_xB);
    cudaGetSymbolAddress((void**)&cnt, g_cnt);
    cudaGetSymbolAddress((void**)&rowptr, g_rowptr);
    cudaGetSymbolAddress((void**)&cursor, g_cursor);
    cudaGetSymbolAddress((void**)&bsum, g_bsum);
    cudaGetSymbolAddress((void**)&eidx, g_eidx);
    cudaGetSymbolAddress((void**)&stats, g_stats);
    cudaGetSymbolAddress((void**)&scale, g_scale);
    cudaGetSymbolAddress((void**)&shift, g_shift);

    const int T = 256;
    int gb = (n + 127) / 128;
    int nb = (n + 2047) / 2048;
    int gwarp = (n + 7) / 8;  // gather: 8 warps/block

    // ---- CSR build (once, reused by all 3 layers) ----
    zero_kernel<<<(n / 4 + T - 1) / T, T>>>((float4*)cnt, n / 4);       // cnt = 0
    zero_kernel<<<(n / 4 + T - 1) / T, T>>>((float4*)cursor, n / 4);    // cursor = 0
    count_kernel<<<(E + T - 1) / T, T>>>(dst, cnt, E);
    scan1_kernel<<<nb, 256>>>(cnt, rowptr, bsum, n);
    scan2_kernel<<<1, 32>>>(bsum, nb);
    scan3_kernel<<<(n + T - 1) / T, T>>>(rowptr, bsum, n);
    fill_kernel<<<(E + T - 1) / T, T>>>(src, dst, rowptr, cursor, eidx, E);

    // ---- layer 0 (DIN = 64) ----
    zero_kernel<<<1, 64>>>((float4*)stats, 64);
    gather_kernel<64><<<gwarp, T>>>(x, eidx, rowptr, cnt, neigh, n);
    gemm_stats_kernel<64><<<gb, T>>>(x, neigh, Ws0, Wn0, b0, h, stats, n);
    bnparam_kernel<<<1, 128>>>(stats, g0, be0, scale, shift, invN);
    bn_relu_kernel<<<(n * 32 + T - 1) / T, T>>>(h, scale, shift, xA, n);

    // ---- layer 1 (DIN = 128) ----
    zero_kernel<<<1, 64>>>((float4*)stats, 64);
    gather_kernel<128><<<gwarp, T>>>(xA, eidx, rowptr, cnt, neigh, n);
    gemm_stats_kernel<128><<<gb, T>>>(xA, neigh, Ws1, Wn1, b1, h, stats, n);
    bnparam_kernel<<<1, 128>>>(stats, g1, be1, scale, shift, invN);
    bn_relu_kernel<<<(n * 32 + T - 1) / T, T>>>(h, scale, shift, xB, n);

    // ---- layer 2 (DIN = 128) + fused BN/ReLU/classifier ----
    zero_kernel<<<1, 64>>>((float4*)stats, 64);
    gather_kernel<128><<<gwarp, T>>>(xB, eidx, rowptr, cnt, neigh, n);
    gemm_stats_kernel<128><<<gb, T>>>(xB, neigh, Ws2, Wn2, b2, h, stats, n);
    bnparam_kernel<<<1, 128>>>(stats, g2, be2, scale, shift, invN);
    bn_cls_kernel<<<(n * 32 + T - 1) / T, T>>>(h, scale, shift, Wc, bc, out, n);
}

// round 7
// speedup vs baseline: 2.7034x; 1.3399x over previous
#include <cuda_runtime.h>
#include <cuda_bf16.h>
#include <mma.h>
#include <cstdint>

using namespace nvcuda;

#define MAXN 100000
#define MAXE 1300000

// ---------------- scratch (static device globals; no allocations allowed) ----
__device__ float g_neigh[MAXN * 128];
__device__ float g_h[MAXN * 128];
__device__ float g_xA[MAXN * 128];
__device__ float g_xB[MAXN * 128];
__device__ int   g_cnt[MAXN];
__device__ int   g_rowptr[MAXN];
__device__ int   g_cursor[MAXN];
__device__ int   g_bsum[128];
__device__ int   g_eidx[MAXE];
__device__ float g_stats[256];   // [0:128) colsum, [128:256) colsumsq
__device__ float g_scale[128];
__device__ float g_shift[128];
__device__ __nv_bfloat16 g_WtB[128 * 256];  // W^T big part   [N=128][K<=256]
__device__ __nv_bfloat16 g_WtS[128 * 256];  // W^T small part

// ---------------- utility kernels -------------------------------------------
__global__ void zero_kernel(float4* p, int n4) {
    int i = blockIdx.x * blockDim.x + threadIdx.x;
    if (i < n4) p[i] = make_float4(0.f, 0.f, 0.f, 0.f);
}

// ---------------- CSR build --------------------------------------------------
__global__ void count_kernel(const int* __restrict__ dst, int* __restrict__ cnt, int E) {
    int e = blockIdx.x * blockDim.x + threadIdx.x;
    if (e < E) atomicAdd(&cnt[dst[e]], 1);
}

__global__ void scan1_kernel(const int* __restrict__ cnt, int* __restrict__ rowptr,
                             int* __restrict__ bsum, int n) {
    __shared__ int sdata[256];
    int b = blockIdx.x, t = threadIdx.x;
    int base = b * 2048 + t * 8;
    int v[8], s = 0;
#pragma unroll
    for (int i = 0; i < 8; i++) {
        int idx = base + i;
        v[i] = (idx < n) ? cnt[idx] : 0;
        s += v[i];
    }
    sdata[t] = s;
    __syncthreads();
    for (int off = 1; off < 256; off <<= 1) {
        int xv = (t >= off) ? sdata[t - off] : 0;
        __syncthreads();
        sdata[t] += xv;
        __syncthreads();
    }
    int run = sdata[t] - s;
    if (t == 255) bsum[b] = sdata[255];
#pragma unroll
    for (int i = 0; i < 8; i++) {
        int idx = base + i;
        if (idx < n) rowptr[idx] = run;
        run += v[i];
    }
}

__global__ void scan2_kernel(int* __restrict__ bsum, int nb) {
    if (threadIdx.x == 0) {
        int s = 0;
        for (int i = 0; i < nb; i++) { int t = bsum[i]; bsum[i] = s; s += t; }
    }
}

__global__ void scan3_kernel(int* __restrict__ rowptr, const int* __restrict__ bsum, int n) {
    int i = blockIdx.x * blockDim.x + threadIdx.x;
    if (i < n) rowptr[i] += bsum[i >> 11];
}

__global__ void fill_kernel(const int* __restrict__ src, const int* __restrict__ dst,
                            const int* __restrict__ rowptr, int* __restrict__ cursor,
                            int* __restrict__ eidx, int E) {
    int e = blockIdx.x * blockDim.x + threadIdx.x;
    if (e < E) {
        int d = dst[e];
        int p = atomicAdd(&cursor[d], 1);
        eidx[rowptr[d] + p] = src[e];
    }
}

// ---------------- mean aggregation via CSR gather ----------------------------
template <int DIM>
__global__ void gather_kernel(const float* __restrict__ x, const int* __restrict__ eidx,
                              const int* __restrict__ rowptr, const int* __restrict__ cnt,
                              float* __restrict__ neigh, int n) {
    int node = blockIdx.x * (blockDim.x >> 5) + (threadIdx.x >> 5);
    int lane = threadIdx.x & 31;
    if (node >= n) return;
    int start = rowptr[node];
    int d = cnt[node];

    if (DIM == 128) {
        float4 a0 = make_float4(0.f, 0.f, 0.f, 0.f);
        float4 a1 = make_float4(0.f, 0.f, 0.f, 0.f);
        int j = 0;
        for (; j + 4 <= d; j += 4) {
            int s0 = eidx[start + j + 0];
            int s1 = eidx[start + j + 1];
            int s2 = eidx[start + j + 2];
            int s3 = eidx[start + j + 3];
            float4 v0 = *reinterpret_cast<const float4*>(x + (size_t)s0 * 128 + lane * 4);
            float4 v1 = *reinterpret_cast<const float4*>(x + (size_t)s1 * 128 + lane * 4);
            float4 v2 = *reinterpret_cast<const float4*>(x + (size_t)s2 * 128 + lane * 4);
            float4 v3 = *reinterpret_cast<const float4*>(x + (size_t)s3 * 128 + lane * 4);
            a0.x += v0.x + v1.x; a0.y += v0.y + v1.y; a0.z += v0.z + v1.z; a0.w += v0.w + v1.w;
            a1.x += v2.x + v3.x; a1.y += v2.y + v3.y; a1.z += v2.z + v3.z; a1.w += v2.w + v3.w;
        }
        for (; j < d; j++) {
            int s = eidx[start + j];
            float4 v = *reinterpret_cast<const float4*>(x + (size_t)s * 128 + lane * 4);
            a0.x += v.x; a0.y += v.y; a0.z += v.z; a0.w += v.w;
        }
        float inv = 1.0f / (float)max(d, 1);
        float4 o;
        o.x = (a0.x + a1.x) * inv; o.y = (a0.y + a1.y) * inv;
        o.z = (a0.z + a1.z) * inv; o.w = (a0.w + a1.w) * inv;
        *reinterpret_cast<float4*>(neigh + (size_t)node * 128 + lane * 4) = o;
    } else {  // DIM == 64
        float2 a0 = make_float2(0.f, 0.f);
        float2 a1 = make_float2(0.f, 0.f);
        int j = 0;
        for (; j + 4 <= d; j += 4) {
            int s0 = eidx[start + j + 0];
            int s1 = eidx[start + j + 1];
            int s2 = eidx[start + j + 2];
            int s3 = eidx[start + j + 3];
            float2 v0 = *reinterpret_cast<const float2*>(x + (size_t)s0 * 64 + lane * 2);
            float2 v1 = *reinterpret_cast<const float2*>(x + (size_t)s1 * 64 + lane * 2);
            float2 v2 = *reinterpret_cast<const float2*>(x + (size_t)s2 * 64 + lane * 2);
            float2 v3 = *reinterpret_cast<const float2*>(x + (size_t)s3 * 64 + lane * 2);
            a0.x += v0.x + v1.x; a0.y += v0.y + v1.y;
            a1.x += v2.x + v3.x; a1.y += v2.y + v3.y;
        }
        for (; j < d; j++) {
            int s = eidx[start + j];
            float2 v = *reinterpret_cast<const float2*>(x + (size_t)s * 64 + lane * 2);
            a0.x += v.x; a0.y += v.y;
        }
        float inv = 1.0f / (float)max(d, 1);
        float2 o;
        o.x = (a0.x + a1.x) * inv; o.y = (a0.y + a1.y) * inv;
        *reinterpret_cast<float2*>(neigh + (size_t)node * 64 + lane * 2) = o;
    }
}

// ---------------- weight transpose + bf16 big/small split --------------------
// Wt[n][k] = W[k][n] where W = [Ws ; Wn] stacked along K.
// big = bf16(v), small = bf16(v - big): 3-term split gives fp32-class accuracy.
__global__ void wsplit_kernel(const float* __restrict__ Ws, const float* __restrict__ Wn,
                              __nv_bfloat16* __restrict__ WtB,
                              __nv_bfloat16* __restrict__ WtS, int DIN) {
    int K = 2 * DIN;
    int idx = blockIdx.x * blockDim.x + threadIdx.x;
    if (idx >= 128 * K) return;
    int nrow = idx / K;
    int k = idx - nrow * K;
    float v = (k < DIN) ? Ws[k * 128 + nrow] : Wn[(k - DIN) * 128 + nrow];
    __nv_bfloat16 b = __float2bfloat16(v);
    float s = v - __bfloat162float(b);
    WtB[idx] = b;
    WtS[idx] = __float2bfloat16(s);
}

// ---------------- wmma bf16 GEMM + BN-stats (3-term split) -------------------
// D[m][n] = sum_k A[m][k] * Wt[n][k],  A = [x | neigh] (K = 2*DIN).
// CTA tile 128x128, 8 warps (2 M x 4 N), warp tile 64x32, BK=32 chunks.
// A is split big/small to bf16 during the smem load; B comes pre-split.
// 3 MMA terms: Ab*Bb + Ab*Bs + As*Bb (dropped As*Bs <= 2^-18).
// Epilogue: fragments -> padded smem -> +bias -> coalesced h stores + per-col
// sum/sumsq stats (smem atomics then 1 global atomic per column per CTA).
#define BKP 40                        // padded tile K-stride (bf16 elements)
#define OFF_AS  10240
#define OFF_BB  20480
#define OFF_BS  30720
#define OFF_ST  67584                 // after sD (128 * 132 * 4 = 67584)
#define OFF_ST2 68096
#define OFF_BI  68608
#define GEMM_SMEM 69120

template <int DIN>
__global__ __launch_bounds__(256) void gemm_wmma_kernel(
    const float* __restrict__ x, const float* __restrict__ neigh,
    const __nv_bfloat16* __restrict__ WtB, const __nv_bfloat16* __restrict__ WtS,
    const float* __restrict__ bias, float* __restrict__ h,
    float* __restrict__ stats, int n) {
    constexpr int K = 2 * DIN;
    constexpr int NC = K / 32;

    extern __shared__ char sm[];
    __nv_bfloat16* sAB = (__nv_bfloat16*)(sm);
    __nv_bfloat16* sAS = (__nv_bfloat16*)(sm + OFF_AS);
    __nv_bfloat16* sBB = (__nv_bfloat16*)(sm + OFF_BB);
    __nv_bfloat16* sBS = (__nv_bfloat16*)(sm + OFF_BS);
    float* sD      = (float*)sm;              // [128][132] (epilogue overlay)
    float* sStats  = (float*)(sm + OFF_ST);
    float* sStats2 = (float*)(sm + OFF_ST2);
    float* sBias   = (float*)(sm + OFF_BI);

    int tid = threadIdx.x;
    int row0 = blockIdx.x * 128;
    if (tid < 128) {
        sStats[tid] = 0.f;
        sStats2[tid] = 0.f;
        sBias[tid] = bias[tid];
    }

    int w = tid >> 5;
    int wm = w & 1;    // rows wm*64 .. +63
    int wn = w >> 1;   // cols wn*32 .. +31

    wmma::fragment<wmma::accumulator, 16, 16, 16, float> acc[4][2];
#pragma unroll
    for (int i = 0; i < 4; i++)
#pragma unroll
        for (int j = 0; j < 2; j++) wmma::fill_fragment(acc[i][j], 0.f);

    for (int c = 0; c < NC; c++) {
        const float* Asrc = (c * 32 < DIN) ? x : neigh;
        int koff = (c * 32 < DIN) ? c * 32 : c * 32 - DIN;

        // ---- A tile: 128 rows x 32 f32, split -> bf16 big/small ----
#pragma unroll
        for (int i = 0; i < 4; i++) {
            int f = tid + i * 256;       // 0..1023 quads
            int row = f >> 3;
            int q = f & 7;               // float4 index along k
            int grow = row0 + row;
            float4 v = make_float4(0.f, 0.f, 0.f, 0.f);
            if (grow < n)
                v = *reinterpret_cast<const float4*>(Asrc + (size_t)grow * DIN + koff + q * 4);
            __nv_bfloat16 b0 = __float2bfloat16(v.x), b1 = __float2bfloat16(v.y);
            __nv_bfloat16 b2 = __float2bfloat16(v.z), b3 = __float2bfloat16(v.w);
            __nv_bfloat16 s0 = __float2bfloat16(v.x - __bfloat162float(b0));
            __nv_bfloat16 s1 = __float2bfloat16(v.y - __bfloat162float(b1));
            __nv_bfloat16 s2 = __float2bfloat16(v.z - __bfloat162float(b2));
            __nv_bfloat16 s3 = __float2bfloat16(v.w - __bfloat162float(b3));
            int o = row * BKP + q * 4;
            *reinterpret_cast<__nv_bfloat162*>(sAB + o)     = __nv_bfloat162(b0, b1);
            *reinterpret_cast<__nv_bfloat162*>(sAB + o + 2) = __nv_bfloat162(b2, b3);
            *reinterpret_cast<__nv_bfloat162*>(sAS + o)     = __nv_bfloat162(s0, s1);
            *reinterpret_cast<__nv_bfloat162*>(sAS + o + 2) = __nv_bfloat162(s2, s3);
        }
        // ---- B tile: 128 N-rows x 32 bf16 from pre-split Wt (16B chunks) ----
#pragma unroll
        for (int i = 0; i < 2; i++) {
            int f = tid + i * 256;       // 0..511 oct-groups
            int row = f >> 2;
            int q = f & 3;               // 8-bf16 group along k
            const uint4* pb = reinterpret_cast<const uint4*>(WtB + (size_t)row * K + c * 32 + q * 8);
            const uint4* ps = reinterpret_cast<const uint4*>(WtS + (size_t)row * K + c * 32 + q * 8);
            *reinterpret_cast<uint4*>(sBB + row * BKP + q * 8) = *pb;
            *reinterpret_cast<uint4*>(sBS + row * BKP + q * 8) = *ps;
        }
        __syncthreads();

#pragma unroll
        for (int ks = 0; ks < 2; ks++) {
            int kk = ks * 16;
            wmma::fragment<wmma::matrix_b, 16, 16, 16, __nv_bfloat16, wmma::col_major> fbB[2], fbS[2];
#pragma unroll
            for (int j = 0; j < 2; j++) {
                wmma::load_matrix_sync(fbB[j], sBB + (wn * 32 + j * 16) * BKP + kk, BKP);
                wmma::load_matrix_sync(fbS[j], sBS + (wn * 32 + j * 16) * BKP + kk, BKP);
            }
#pragma unroll
            for (int i = 0; i < 4; i++) {
                wmma::fragment<wmma::matrix_a, 16, 16, 16, __nv_bfloat16, wmma::row_major> faB, faS;
                wmma::load_matrix_sync(faB, sAB + (wm * 64 + i * 16) * BKP + kk, BKP);
                wmma::load_matrix_sync(faS, sAS + (wm * 64 + i * 16) * BKP + kk, BKP);
#pragma unroll
                for (int j = 0; j < 2; j++) {
                    wmma::mma_sync(acc[i][j], faB, fbB[j], acc[i][j]);
                    wmma::mma_sync(acc[i][j], faB, fbS[j], acc[i][j]);
                    wmma::mma_sync(acc[i][j], faS, fbB[j], acc[i][j]);
                }
            }
        }
        __syncthreads();
    }

    // ---- epilogue: fragments -> smem (stride 132), +bias, h stores, stats ----
#pragma unroll
    for (int i = 0; i < 4; i++)
#pragma unroll
        for (int j = 0; j < 2; j++)
            wmma::store_matrix_sync(sD + (wm * 64 + i * 16) * 132 + wn * 32 + j * 16,
                                    acc[i][j], 132, wmma::mem_row_major);
    __syncthreads();
    {
        int cq = tid & 31;   // column quad: cols cq*4 .. +3
        int wr = tid >> 5;   // row stride-8 phase
        float4 bi = *reinterpret_cast<const float4*>(sBias + cq * 4);
        float ps0 = 0.f, ps1 = 0.f, ps2 = 0.f, ps3 = 0.f;
        float pq0 = 0.f, pq1 = 0.f, pq2 = 0.f, pq3 = 0.f;
#pragma unroll
        for (int it = 0; it < 16; it++) {
            int r = wr + it * 8;
            int grow = row0 + r;
            if (grow < n) {
                float v0 = sD[r * 132 + cq * 4 + 0] + bi.x;
                float v1 = sD[r * 132 + cq * 4 + 1] + bi.y;
                float v2 = sD[r * 132 + cq * 4 + 2] + bi.z;
                float v3 = sD[r * 132 + cq * 4 + 3] + bi.w;
                *reinterpret_cast<float4*>(h + (size_t)grow * 128 + cq * 4) =
                    make_float4(v0, v1, v2, v3);
                ps0 += v0; ps1 += v1; ps2 += v2; ps3 += v3;
                pq0 += v0 * v0; pq1 += v1 * v1; pq2 += v2 * v2; pq3 += v3 * v3;
            }
        }
        atomicAdd(&sStats[cq * 4 + 0], ps0); atomicAdd(&sStats2[cq * 4 + 0], pq0);
        atomicAdd(&sStats[cq * 4 + 1], ps1); atomicAdd(&sStats2[cq * 4 + 1], pq1);
        atomicAdd(&sStats[cq * 4 + 2], ps2); atomicAdd(&sStats2[cq * 4 + 2], pq2);
        atomicAdd(&sStats[cq * 4 + 3], ps3); atomicAdd(&sStats2[cq * 4 + 3], pq3);
    }
    __syncthreads();
    if (tid < 128) {
        atomicAdd(&stats[tid], sStats[tid]);
        atomicAdd(&stats[128 + tid], sStats2[tid]);
    }
}

// ---------------- BN parameter folding --------------------------------------
__global__ void bnparam_kernel(const float* __restrict__ stats, const float* __restrict__ gamma,
                               const float* __restrict__ beta, float* __restrict__ scale,
                               float* __restrict__ shift, float invN) {
    int j = threadIdx.x;
    float mu = stats[j] * invN;
    float var = stats[128 + j] * invN - mu * mu;
    float sc = gamma[j] * rsqrtf(var + 1e-5f);
    scale[j] = sc;
    shift[j] = fmaf(-mu, sc, beta[j]);
}

// ---------------- BN apply + ReLU (elementwise, float4) ---------------------
__global__ void bn_relu_kernel(const float* __restrict__ h, const float* __restrict__ scale,
                               const float* __restrict__ shift, float* __restrict__ out, int n) {
    int idx = blockIdx.x * blockDim.x + threadIdx.x;
    if (idx >= n * 32) return;
    int j4 = idx & 31;
    float4 v = reinterpret_cast<const float4*>(h)[idx];
    float4 sc = reinterpret_cast<const float4*>(scale)[j4];
    float4 sh = reinterpret_cast<const float4*>(shift)[j4];
    float4 o;
    o.x = fmaxf(fmaf(v.x, sc.x, sh.x), 0.f);
    o.y = fmaxf(fmaf(v.y, sc.y, sh.y), 0.f);
    o.z = fmaxf(fmaf(v.z, sc.z, sh.z), 0.f);
    o.w = fmaxf(fmaf(v.w, sc.w, sh.w), 0.f);
    reinterpret_cast<float4*>(out)[idx] = o;
}

// ---------------- fused BN + ReLU + classifier (final layer) ----------------
__global__ void bn_cls_kernel(const float* __restrict__ h, const float* __restrict__ scale,
                              const float* __restrict__ shift, const float* __restrict__ Wc,
                              const float* __restrict__ bc, float* __restrict__ out, int n) {
    int warp = (blockIdx.x * blockDim.x + threadIdx.x) >> 5;
    int lane = threadIdx.x & 31;
    if (warp >= n) return;
    float4 v = reinterpret_cast<const float4*>(h + (size_t)warp * 128)[lane];
    float4 sc = reinterpret_cast<const float4*>(scale)[lane];
    float4 sh = reinterpret_cast<const float4*>(shift)[lane];
    int c = lane * 4;
    float w0 = fmaxf(fmaf(v.x, sc.x, sh.x), 0.f);
    float w1 = fmaxf(fmaf(v.y, sc.y, sh.y), 0.f);
    float w2 = fmaxf(fmaf(v.z, sc.z, sh.z), 0.f);
    float w3 = fmaxf(fmaf(v.w, sc.w, sh.w), 0.f);
    float a0 = w0 * Wc[(c + 0) * 2 + 0] + w1 * Wc[(c + 1) * 2 + 0] +
               w2 * Wc[(c + 2) * 2 + 0] + w3 * Wc[(c + 3) * 2 + 0];
    float a1 = w0 * Wc[(c + 0) * 2 + 1] + w1 * Wc[(c + 1) * 2 + 1] +
               w2 * Wc[(c + 2) * 2 + 1] + w3 * Wc[(c + 3) * 2 + 1];
#pragma unroll
    for (int off = 16; off; off >>= 1) {
        a0 += __shfl_xor_sync(0xffffffffu, a0, off);
        a1 += __shfl_xor_sync(0xffffffffu, a1, off);
    }
    if (lane == 0) {
        out[(size_t)warp * 2 + 0] = a0 + bc[0];
        out[(size_t)warp * 2 + 1] = a1 + bc[1];
    }
}

// ---------------- host entry -------------------------------------------------
extern "C" void kernel_launch(void* const* d_in, const int* in_sizes, int n_in,
                              void* d_out, int out_size) {
    const float* x = (const float*)d_in[0];
    const int* src = (const int*)d_in[1];
    const int* dst = (const int*)d_in[2];
    const float* Ws0 = (const float*)d_in[3];
    const float* b0 = (const float*)d_in[4];
    const float* Wn0 = (const float*)d_in[5];
    const float* g0 = (const float*)d_in[6];
    const float* be0 = (const float*)d_in[7];
    const float* Ws1 = (const float*)d_in[8];
    const float* b1 = (const float*)d_in[9];
    const float* Wn1 = (const float*)d_in[10];
    const float* g1 = (const float*)d_in[11];
    const float* be1 = (const float*)d_in[12];
    const float* Ws2 = (const float*)d_in[13];
    const float* b2 = (const float*)d_in[14];
    const float* Wn2 = (const float*)d_in[15];
    const float* g2 = (const float*)d_in[16];
    const float* be2 = (const float*)d_in[17];
    const float* Wc = (const float*)d_in[18];
    const float* bc = (const float*)d_in[19];
    float* out = (float*)d_out;

    int n = in_sizes[0] / 64;
    int E = in_sizes[1];
    float invN = 1.0f / (float)n;

    float *neigh, *h, *xA, *xB, *stats, *scale, *shift;
    __nv_bfloat16 *WtB, *WtS;
    int *cnt, *rowptr, *cursor, *bsum, *eidx;
    cudaGetSymbolAddress((void**)&neigh, g_neigh);
    cudaGetSymbolAddress((void**)&h, g_h);
    cudaGetSymbolAddress((void**)&xA, g_xA);
    cudaGetSymbolAddress((void**)&xB, g_xB);
    cudaGetSymbolAddress((void**)&cnt, g_cnt);
    cudaGetSymbolAddress((void**)&rowptr, g_rowptr);
    cudaGetSymbolAddress((void**)&cursor, g_cursor);
    cudaGetSymbolAddress((void**)&bsum, g_bsum);
    cudaGetSymbolAddress((void**)&eidx, g_eidx);
    cudaGetSymbolAddress((void**)&stats, g_stats);
    cudaGetSymbolAddress((void**)&scale, g_scale);
    cudaGetSymbolAddress((void**)&shift, g_shift);
    cudaGetSymbolAddress((void**)&WtB, g_WtB);
    cudaGetSymbolAddress((void**)&WtS, g_WtS);

    cudaFuncSetAttribute(gemm_wmma_kernel<64>,
                         cudaFuncAttributeMaxDynamicSharedMemorySize, GEMM_SMEM);
    cudaFuncSetAttribute(gemm_wmma_kernel<128>,
                         cudaFuncAttributeMaxDynamicSharedMemorySize, GEMM_SMEM);

    const int T = 256;
    int gb = (n + 127) / 128;
    int nb = (n + 2047) / 2048;
    int gwarp = (n + 7) / 8;

    // ---- CSR build (once, reused by all 3 layers) ----
    zero_kernel<<<(n / 4 + T - 1) / T, T>>>((float4*)cnt, n / 4);
    zero_kernel<<<(n / 4 + T - 1) / T, T>>>((float4*)cursor, n / 4);
    count_kernel<<<(E + T - 1) / T, T>>>(dst, cnt, E);
    scan1_kernel<<<nb, 256>>>(cnt, rowptr, bsum, n);
    scan2_kernel<<<1, 32>>>(bsum, nb);
    scan3_kernel<<<(n + T - 1) / T, T>>>(rowptr, bsum, n);
    fill_kernel<<<(E + T - 1) / T, T>>>(src, dst, rowptr, cursor, eidx, E);

    // ---- layer 0 (DIN = 64) ----
    zero_kernel<<<1, 64>>>((float4*)stats, 64);
    wsplit_kernel<<<(128 * 128 + T - 1) / T, T>>>(Ws0, Wn0, WtB, WtS, 64);
    gather_kernel<64><<<gwarp, T>>>(x, eidx, rowptr, cnt, neigh, n);
    gemm_wmma_kernel<64><<<gb, T, GEMM_SMEM>>>(x, neigh, WtB, WtS, b0, h, stats, n);
    bnparam_kernel<<<1, 128>>>(stats, g0, be0, scale, shift, invN);
    bn_relu_kernel<<<(n * 32 + T - 1) / T, T>>>(h, scale, shift, xA, n);

    // ---- layer 1 (DIN = 128) ----
    zero_kernel<<<1, 64>>>((float4*)stats, 64);
    wsplit_kernel<<<(128 * 256 + T - 1) / T, T>>>(Ws1, Wn1, WtB, WtS, 128);
    gather_kernel<128><<<gwarp, T>>>(xA, eidx, rowptr, cnt, neigh, n);
    gemm_wmma_kernel<128><<<gb, T, GEMM_SMEM>>>(xA, neigh, WtB, WtS, b1, h, stats, n);
    bnparam_kernel<<<1, 128>>>(stats, g1, be1, scale, shift, invN);
    bn_relu_kernel<<<(n * 32 + T - 1) / T, T>>>(h, scale, shift, xB, n);

    // ---- layer 2 (DIN = 128) + fused BN/ReLU/classifier ----
    zero_kernel<<<1, 64>>>((float4*)stats, 64);
    wsplit_kernel<<<(128 * 256 + T - 1) / T, T>>>(Ws2, Wn2, WtB, WtS, 128);
    gather_kernel<128><<<gwarp, T>>>(xB, eidx, rowptr, cnt, neigh, n);
    gemm_wmma_kernel<128><<<gb, T, GEMM_SMEM>>>(xB, neigh, WtB, WtS, b2, h, stats, n);
    bnparam_kernel<<<1, 128>>>(stats, g2, be2, scale, shift, invN);
    bn_cls_kernel<<<(n * 32 + T - 1) / T, T>>>(h, scale, shift, Wc, bc, out, n);
}